// round 3
// baseline (speedup 1.0000x reference)
#include <cuda_runtime.h>
#include <cstdint>
#include <cstddef>

// 3-layer LSTM (PyTorch gate order i,f,g,o), batch-parallel, layer-sequential.
// Each CTA owns Bc=2 batch columns for all T=512 steps of one layer.
// Gate row weights live in REGISTERS (one row per thread, fully unrolled),
// dot products use packed fma.rn.f32x2 (k-packing) at full fp32 rate.
// Inter-layer activations staged in __device__ global buffers (no allocs).
//
// Round-1 fix (still in effect): x (token ids) is int32 — JAX's default
// x64-disabled mode makes jnp.int64 silently int32. Reading it as int64
// caused the Round-0 illegal access.
// Round-2: resubmission — previous bench died to a broker/container failure
// before running the kernel; no kernel-side signal to act on.

#define T_SEQ   512
#define BATCH   256
#define HID     64
#define GATES   256   // 4*HID
#define EMBD    128
#define VOCAB   50257
#define BC      2
#define NCTA    (BATCH / BC)   // 128
#define NTHREADS 256

__device__ float g_h1[(size_t)T_SEQ * BATCH * HID];
__device__ float g_h2[(size_t)T_SEQ * BATCH * HID];

typedef unsigned long long ull;

__device__ __forceinline__ ull pack2(float x, float y) {
    ull r;
    asm("mov.b64 %0, {%1,%2};" : "=l"(r) : "f"(x), "f"(y));
    return r;
}
__device__ __forceinline__ void fma2(ull& acc, ull a, ull b) {
    asm("fma.rn.f32x2 %0, %1, %2, %0;" : "+l"(acc) : "l"(a), "l"(b));
}
__device__ __forceinline__ float red2(ull a) {
    float lo, hi;
    asm("mov.b64 {%0,%1}, %2;" : "=f"(lo), "=f"(hi) : "l"(a));
    return lo + hi;
}
// Numerically safe fast sigmoid / tanh built on MUFU ex2 path.
__device__ __forceinline__ float fsigm(float x) {
    return __fdividef(1.0f, 1.0f + __expf(-x));
}
__device__ __forceinline__ float ftanh(float x) {
    float e = __expf(-2.0f * fabsf(x));     // in (0,1], no overflow
    float t = __fdividef(1.0f - e, 1.0f + e);
    return copysignf(t, x);
}

// MODE 0: layer1 (embedding gather input, writes g_h1)
// MODE 1: layer2 (reads g_h1, writes g_h2)
// MODE 2: layer3 (reads g_h2, fused softmax -> out_sm)
template <int KIN, int MODE>
__global__ void __launch_bounds__(NTHREADS, 1)
lstm_layer_kernel(const int* __restrict__ xidx,
                  const float* __restrict__ emb,
                  const float* __restrict__ W_ih,
                  const float* __restrict__ W_hh,
                  const float* __restrict__ b_ih,
                  const float* __restrict__ b_hh,
                  float* __restrict__ out_sm)
{
    constexpr int KTOT = KIN + HID;          // 192 (L1) or 128 (L2/L3)
    __shared__ __align__(16) float xh[BC][KTOT];   // [x_t | h_{t-1}] per batch col
    __shared__ float gsm[BC][GATES];               // gate pre-activations
    __shared__ int   idxs[BC][T_SEQ];              // token ids (MODE 0 only)

    const int tid = threadIdx.x;
    const int row = tid;                      // gate row 0..255
    const int b0  = blockIdx.x * BC;

    const float* seq_in = (MODE == 1) ? g_h1 : g_h2;   // unused for MODE 0
    float* out_h = (MODE == 0) ? g_h1 : g_h2;          // unused for MODE 2

    // ---- load this thread's gate-row weights into registers (as f32x2 pairs)
    ull w2[KTOT / 2];
    {
        const float4* wi = reinterpret_cast<const float4*>(W_ih + (size_t)row * KIN);
        #pragma unroll
        for (int q = 0; q < KIN / 4; q++) {
            float4 v = wi[q];
            w2[2 * q]     = pack2(v.x, v.y);
            w2[2 * q + 1] = pack2(v.z, v.w);
        }
        const float4* wh = reinterpret_cast<const float4*>(W_hh + (size_t)row * HID);
        #pragma unroll
        for (int q = 0; q < HID / 4; q++) {
            float4 v = wh[q];
            w2[KIN / 2 + 2 * q]     = pack2(v.x, v.y);
            w2[KIN / 2 + 2 * q + 1] = pack2(v.z, v.w);
        }
    }
    const float bs = b_ih[row] + b_hh[row];

    // ---- token indices for our batch columns (MODE 0). Clamp defensively.
    if (MODE == 0) {
        for (int i = tid; i < BC * T_SEQ; i += NTHREADS) {
            int b = i >> 9;            // / T_SEQ
            int t = i & (T_SEQ - 1);   // % T_SEQ
            int v = xidx[(size_t)t * BATCH + b0 + b];
            v = v < 0 ? 0 : (v >= VOCAB ? VOCAB - 1 : v);
            idxs[b][t] = v;
        }
    }

    // ---- init h_{-1} = 0, c = 0
    float c = 0.0f;
    if (tid < BC * HID) {
        int b = tid >> 6, j = tid & 63;
        xh[b][KIN + j] = 0.0f;
    }
    __syncthreads();

    // ---- load x_0
    if (MODE == 0) {
        int b = tid >> 7, k = tid & 127;
        xh[b][k] = emb[(size_t)idxs[b][0] * EMBD + k];
    } else {
        if (tid < BC * HID) {
            int b = tid >> 6, k = tid & 63;
            xh[b][k] = seq_in[(size_t)(b0 + b) * HID + k];
        }
    }
    __syncthreads();

    for (int t = 0; t < T_SEQ; t++) {
        // ---- prefetch x_{t+1} into registers (hidden under the dot)
        float px = 0.0f;
        int pb = 0, pk = 0;
        bool havepx = false;
        if (t + 1 < T_SEQ) {
            if (MODE == 0) {
                pb = tid >> 7; pk = tid & 127;
                px = emb[(size_t)idxs[pb][t + 1] * EMBD + pk];
                havepx = true;
            } else if (tid >= 128) {
                int e = tid - 128;
                pb = e >> 6; pk = e & 63;
                px = seq_in[((size_t)(t + 1) * BATCH + b0 + pb) * HID + pk];
                havepx = true;
            }
        }

        // ---- dot: g[b][row] = sum_k Wcat[row][k] * xh[b][k]
        ull acc0 = 0ull, acc1 = 0ull;
        const ulonglong2* x0p = reinterpret_cast<const ulonglong2*>(&xh[0][0]);
        const ulonglong2* x1p = reinterpret_cast<const ulonglong2*>(&xh[1][0]);
        #pragma unroll
        for (int q = 0; q < KTOT / 4; q++) {
            ulonglong2 a = x0p[q];
            ulonglong2 bb = x1p[q];
            fma2(acc0, w2[2 * q],     a.x);
            fma2(acc0, w2[2 * q + 1], a.y);
            fma2(acc1, w2[2 * q],     bb.x);
            fma2(acc1, w2[2 * q + 1], bb.y);
        }
        gsm[0][row] = red2(acc0) + bs;
        gsm[1][row] = red2(acc1) + bs;
        __syncthreads();

        // ---- elementwise cell update (threads 0..127: one (j,b) each)
        if (tid < BC * HID) {
            int b = tid >> 6, j = tid & 63;
            float gi = gsm[b][j];
            float gf = gsm[b][HID + j];
            float gg = gsm[b][2 * HID + j];
            float go = gsm[b][3 * HID + j];
            c = fsigm(gf) * c + fsigm(gi) * ftanh(gg);
            float h = fsigm(go) * ftanh(c);
            xh[b][KIN + j] = h;
            if (MODE != 2) {
                out_h[((size_t)t * BATCH + b0 + b) * HID + j] = h;
            }
        }
        // ---- commit prefetched x_{t+1} (x region free after the dot)
        if (havepx) xh[pb][pk] = px;
        __syncthreads();

        // ---- fused softmax over HID (MODE 2)
        if (MODE == 2) {
            int w = tid >> 5, lane = tid & 31;
            if (w < BC) {
                float h0 = xh[w][KIN + lane];
                float h1 = xh[w][KIN + 32 + lane];
                float m = fmaxf(h0, h1);
                #pragma unroll
                for (int off = 16; off > 0; off >>= 1)
                    m = fmaxf(m, __shfl_xor_sync(0xffffffffu, m, off));
                float e0 = __expf(h0 - m);
                float e1 = __expf(h1 - m);
                float s = e0 + e1;
                #pragma unroll
                for (int off = 16; off > 0; off >>= 1)
                    s += __shfl_xor_sync(0xffffffffu, s, off);
                float inv = __fdividef(1.0f, s);
                size_t base = ((size_t)t * BATCH + b0 + w) * HID;
                out_sm[base + lane]      = e0 * inv;
                out_sm[base + 32 + lane] = e1 * inv;
            }
        }
    }
}

extern "C" void kernel_launch(void* const* d_in, const int* in_sizes, int n_in,
                              void* d_out, int out_size)
{
    const int*   x      = (const int*)d_in[0];     // int32! (JAX x64 disabled)
    const float* emb    = (const float*)d_in[1];
    const float* W_ih1  = (const float*)d_in[2];
    const float* W_hh1  = (const float*)d_in[3];
    const float* b_ih1  = (const float*)d_in[4];
    const float* b_hh1  = (const float*)d_in[5];
    const float* W_ih2  = (const float*)d_in[6];
    const float* W_hh2  = (const float*)d_in[7];
    const float* b_ih2  = (const float*)d_in[8];
    const float* b_hh2  = (const float*)d_in[9];
    const float* W_ih3  = (const float*)d_in[10];
    const float* W_hh3  = (const float*)d_in[11];
    const float* b_ih3  = (const float*)d_in[12];
    const float* b_hh3  = (const float*)d_in[13];
    float* out = (float*)d_out;

    lstm_layer_kernel<EMBD, 0><<<NCTA, NTHREADS>>>(x, emb, W_ih1, W_hh1, b_ih1, b_hh1, out);
    lstm_layer_kernel<HID,  1><<<NCTA, NTHREADS>>>(x, emb, W_ih2, W_hh2, b_ih2, b_hh2, out);
    lstm_layer_kernel<HID,  2><<<NCTA, NTHREADS>>>(x, emb, W_ih3, W_hh3, b_ih3, b_hh3, out);
}